// round 1
// baseline (speedup 1.0000x reference)
#include <cuda_runtime.h>
#include <math.h>

#define NSTEP 256
#define W 256
#define Hh 256
#define Dd 256

__device__ __forceinline__ float safe_inv(float d) {
    const float EPSF = 1e-8f;
    // replicate: where(|d|<EPS, sign(d)*EPS+EPS, d)
    float s = (d > 0.f) ? 1.f : ((d < 0.f) ? -1.f : 0.f);
    float w = (fabsf(d) < EPSF) ? fmaf(s, EPSF, EPSF) : d;
    return 1.0f / w;
}

__global__ void __launch_bounds__(256)
transmittance_kernel(const float* __restrict__ rays,
                     const float* __restrict__ grid,
                     float* __restrict__ out,
                     int n_rays)
{
    const float EPSF = 1e-8f;
    int gwarp = (int)((blockIdx.x * 256u + threadIdx.x) >> 5);
    int lane  = threadIdx.x & 31;
    if (gwarp >= n_rays) return;

    // All lanes read the same 6 floats (broadcast)
    const float* r = rays + (size_t)gwarp * 6;
    float ox = __ldg(r + 0), oy = __ldg(r + 1), oz = __ldg(r + 2);
    float dx = __ldg(r + 3), dy = __ldg(r + 4), dz = __ldg(r + 5);

    float nrm = sqrtf(fmaf(dx, dx, fmaf(dy, dy, dz * dz))) + EPSF;
    float inv_n = 1.0f / nrm;
    dx *= inv_n; dy *= inv_n; dz *= inv_n;

    float ix = safe_inv(dx), iy = safe_inv(dy), iz = safe_inv(dz);
    float tax = (-1.f - ox) * ix, tbx = (1.f - ox) * ix;
    float tay = (-1.f - oy) * iy, tby = (1.f - oy) * iy;
    float taz = (-1.f - oz) * iz, tbz = (1.f - oz) * iz;

    float tmin = fmaxf(fmaxf(fminf(tax, tbx), fminf(tay, tby)), fminf(taz, tbz));
    float tmax = fminf(fminf(fmaxf(tax, tbx), fmaxf(tay, tby)), fmaxf(taz, tbz));
    tmin = fmaxf(tmin, 0.0f);

    bool valid = (tmax > tmin);
    if (!valid) {                       // uniform per warp: whole warp exits
        if (lane == 0) out[gwarp] = 1.0f;
        return;
    }
    float seg = tmax - tmin;

    float sum = 0.0f;
    #pragma unroll 4
    for (int it = 0; it < NSTEP / 32; ++it) {
        int i = it * 32 + lane;         // 32 consecutive steps per warp instruction
        float frac = ((float)i + 0.5f) * (1.0f / (float)NSTEP);
        float t = fmaf(seg, frac, tmin);

        float gx = (fmaf(t, dx, ox) + 1.0f) * (0.5f * (W  - 1));
        float gy = (fmaf(t, dy, oy) + 1.0f) * (0.5f * (Hh - 1));
        float gz = (fmaf(t, dz, oz) + 1.0f) * (0.5f * (Dd - 1));

        float x0f = fminf(fmaxf(floorf(gx), 0.f), (float)(W  - 2));
        float y0f = fminf(fmaxf(floorf(gy), 0.f), (float)(Hh - 2));
        float z0f = fminf(fmaxf(floorf(gz), 0.f), (float)(Dd - 2));
        float fx = __saturatef(gx - x0f);
        float fy = __saturatef(gy - y0f);
        float fz = __saturatef(gz - z0f);
        int x0 = (int)x0f, y0 = (int)y0f, z0 = (int)z0f;

        int base = (z0 << 16) + (y0 << 8) + x0;

        // 8 independent corner loads (MLP=8 per iteration)
        float c000 = __saturatef(__ldg(grid + base));
        float c001 = __saturatef(__ldg(grid + base + 1));
        float c010 = __saturatef(__ldg(grid + base + 256));
        float c011 = __saturatef(__ldg(grid + base + 257));
        float c100 = __saturatef(__ldg(grid + base + 65536));
        float c101 = __saturatef(__ldg(grid + base + 65537));
        float c110 = __saturatef(__ldg(grid + base + 65792));
        float c111 = __saturatef(__ldg(grid + base + 65793));

        float c00 = fmaf(c001 - c000, fx, c000);
        float c01 = fmaf(c011 - c010, fx, c010);
        float c10 = fmaf(c101 - c100, fx, c100);
        float c11 = fmaf(c111 - c110, fx, c110);
        float c0  = fmaf(c01 - c00, fy, c00);
        float c1  = fmaf(c11 - c10, fy, c10);
        sum += fmaf(c1 - c0, fz, c0);
    }

    // warp reduction of sigma sum
    #pragma unroll
    for (int o = 16; o; o >>= 1)
        sum += __shfl_xor_sync(0xffffffffu, sum, o);

    if (lane == 0) {
        float dt = seg * (1.0f / (float)NSTEP);
        float tau = 10.0f * sum * dt;
        out[gwarp] = expf(-tau);
    }
}

extern "C" void kernel_launch(void* const* d_in, const int* in_sizes, int n_in,
                              void* d_out, int out_size)
{
    const float* rays = (const float*)d_in[0];
    const float* grid = (const float*)d_in[1];
    float* out = (float*)d_out;
    int n_rays = in_sizes[0] / 6;

    int total_threads = n_rays * 32;           // one warp per ray
    int block = 256;
    int nblocks = (total_threads + block - 1) / block;
    transmittance_kernel<<<nblocks, block>>>(rays, grid, out, n_rays);
}

// round 2
// speedup vs baseline: 1.0656x; 1.0656x over previous
#include <cuda_runtime.h>
#include <cuda_fp16.h>
#include <math.h>

#define NSTEP 256
#define W 256
#define Hh 256
#define Dd 256

// Packed grid: Y[z][y][x] = ( sat(g[z][y][x]), sat(g[z][y+1][x]) )  as half2.
// 256^3 * 4B = 64 MB, L2-resident on GB300 (126 MB L2).
__device__ __half2 g_Y[256 * 256 * 256];

// ---------------- Pre-pass: fp32 grid -> saturated half2 y-pair layout ----------------
__global__ void __launch_bounds__(256)
pack_kernel(const float* __restrict__ g)
{
    // Each thread packs 4 consecutive x voxels (16B load x2, 16B store).
    int idx = blockIdx.x * 256 + threadIdx.x;     // 4,194,304 threads total
    int lin = idx << 2;                            // linear voxel index (x fastest)
    int y = (lin >> 8) & 255;
    int zy1 = (y < 255) ? (lin + 256) : lin;       // row y+1 (clamped) same z,x

    float4 r0 = *reinterpret_cast<const float4*>(g + lin);
    float4 r1 = *reinterpret_cast<const float4*>(g + zy1);

    __half2 h0 = __floats2half2_rn(__saturatef(r0.x), __saturatef(r1.x));
    __half2 h1 = __floats2half2_rn(__saturatef(r0.y), __saturatef(r1.y));
    __half2 h2 = __floats2half2_rn(__saturatef(r0.z), __saturatef(r1.z));
    __half2 h3 = __floats2half2_rn(__saturatef(r0.w), __saturatef(r1.w));

    uint4 pack;
    pack.x = *reinterpret_cast<unsigned int*>(&h0);
    pack.y = *reinterpret_cast<unsigned int*>(&h1);
    pack.z = *reinterpret_cast<unsigned int*>(&h2);
    pack.w = *reinterpret_cast<unsigned int*>(&h3);
    *reinterpret_cast<uint4*>(g_Y + lin) = pack;
}

// ---------------- Main kernel: warp per ray, lane = step index ----------------
__device__ __forceinline__ float safe_inv(float d) {
    const float EPSF = 1e-8f;
    float s = (d > 0.f) ? 1.f : ((d < 0.f) ? -1.f : 0.f);
    float w = (fabsf(d) < EPSF) ? fmaf(s, EPSF, EPSF) : d;
    return 1.0f / w;
}

__global__ void __launch_bounds__(256)
transmittance_kernel(const float* __restrict__ rays,
                     float* __restrict__ out,
                     int n_rays)
{
    const float EPSF = 1e-8f;
    int gwarp = (int)((blockIdx.x * 256u + threadIdx.x) >> 5);
    int lane  = threadIdx.x & 31;
    if (gwarp >= n_rays) return;

    const float* r = rays + (size_t)gwarp * 6;
    float ox = __ldg(r + 0), oy = __ldg(r + 1), oz = __ldg(r + 2);
    float dx = __ldg(r + 3), dy = __ldg(r + 4), dz = __ldg(r + 5);

    float nrm = sqrtf(fmaf(dx, dx, fmaf(dy, dy, dz * dz))) + EPSF;
    float inv_n = 1.0f / nrm;
    dx *= inv_n; dy *= inv_n; dz *= inv_n;

    float ix = safe_inv(dx), iy = safe_inv(dy), iz = safe_inv(dz);
    float tax = (-1.f - ox) * ix, tbx = (1.f - ox) * ix;
    float tay = (-1.f - oy) * iy, tby = (1.f - oy) * iy;
    float taz = (-1.f - oz) * iz, tbz = (1.f - oz) * iz;

    float tmin = fmaxf(fmaxf(fminf(tax, tbx), fminf(tay, tby)), fminf(taz, tbz));
    float tmax = fminf(fminf(fmaxf(tax, tbx), fmaxf(tay, tby)), fmaxf(taz, tbz));
    tmin = fmaxf(tmin, 0.0f);

    bool valid = (tmax > tmin);
    if (!valid) {                       // uniform across the warp
        if (lane == 0) out[gwarp] = 1.0f;
        return;
    }
    float seg = tmax - tmin;

    const __half2* __restrict__ Y = g_Y;
    float sum = 0.0f;

    #pragma unroll 4
    for (int it = 0; it < NSTEP / 32; ++it) {
        int i = it * 32 + lane;          // 32 consecutive steps per warp-instruction
        float frac = ((float)i + 0.5f) * (1.0f / (float)NSTEP);
        float t = fmaf(seg, frac, tmin);

        float gx = (fmaf(t, dx, ox) + 1.0f) * (0.5f * (W  - 1));
        float gy = (fmaf(t, dy, oy) + 1.0f) * (0.5f * (Hh - 1));
        float gz = (fmaf(t, dz, oz) + 1.0f) * (0.5f * (Dd - 1));

        float x0f = fminf(fmaxf(floorf(gx), 0.f), (float)(W  - 2));
        float y0f = fminf(fmaxf(floorf(gy), 0.f), (float)(Hh - 2));
        float z0f = fminf(fmaxf(floorf(gz), 0.f), (float)(Dd - 2));
        float fx = __saturatef(gx - x0f);
        float fy = __saturatef(gy - y0f);
        float fz = __saturatef(gz - z0f);
        int x0 = (int)x0f, y0 = (int)y0f, z0 = (int)z0f;

        int base = (z0 << 16) + (y0 << 8) + x0;

        // 4 loads fetch all 8 corners (y-pairs packed in half2)
        __half2 a = __ldg(Y + base);          // (c000, c010)
        __half2 b = __ldg(Y + base + 1);      // (c001, c011)
        __half2 c = __ldg(Y + base + 65536);  // (c100, c110)
        __half2 d = __ldg(Y + base + 65537);  // (c101, c111)

        float2 A = __half22float2(a);
        float2 B = __half22float2(b);
        float2 C = __half22float2(c);
        float2 D = __half22float2(d);

        float c00 = fmaf(B.x - A.x, fx, A.x);
        float c01 = fmaf(B.y - A.y, fx, A.y);
        float c10 = fmaf(D.x - C.x, fx, C.x);
        float c11 = fmaf(D.y - C.y, fx, C.y);
        float c0  = fmaf(c01 - c00, fy, c00);
        float c1  = fmaf(c11 - c10, fy, c10);
        sum += fmaf(c1 - c0, fz, c0);
    }

    #pragma unroll
    for (int o = 16; o; o >>= 1)
        sum += __shfl_xor_sync(0xffffffffu, sum, o);

    if (lane == 0) {
        float dt = seg * (1.0f / (float)NSTEP);
        float tau = 10.0f * sum * dt;
        out[gwarp] = expf(-tau);
    }
}

extern "C" void kernel_launch(void* const* d_in, const int* in_sizes, int n_in,
                              void* d_out, int out_size)
{
    const float* rays = (const float*)d_in[0];
    const float* grid = (const float*)d_in[1];
    float* out = (float*)d_out;
    int n_rays = in_sizes[0] / 6;

    // Pre-pass: 256^3 voxels, 4 per thread
    int pack_threads = (256 * 256 * 256) / 4;
    pack_kernel<<<pack_threads / 256, 256>>>(grid);

    // Main: one warp per ray
    int total_threads = n_rays * 32;
    transmittance_kernel<<<(total_threads + 255) / 256, 256>>>(rays, out, n_rays);
}